// round 7
// baseline (speedup 1.0000x reference)
#include <cuda_runtime.h>
#include <cuda_bf16.h>

// RZGate, L=12, D=2, J=1. S = diag(1,-1) deterministically, so
// U = kron_i diag(e^{-i a_i/2}, e^{+i a_i/2}) is DIAGONAL:
//   theta(row) = -0.5 * sum_i a_i * (bit_i(row) ? -1 : +1)   (site 0 = MSB)
//   out[row,b] = (cos th + i sin th) * x[row,b]
//
// ABI-adaptive version:
//  * output mode chosen from out_size on the host:
//      out_size >= 2*NELEMS -> interleaved (re,im) float pairs (8 MB)
//      out_size == NELEMS   -> float32 REAL PART only (4 MB)  [numpy
//                              complex64->float32 cast takes the real part]
//  * x/angle dtype (f32 vs bf16) probed at runtime from x's bit pattern;
//    reads bounded to min(in_sizes, NELEMS) ELEMENTS of the detected dtype
//    (safe under element-count or byte-count conventions, either dtype).
//  * scalar loads/stores only -> immune to sub-allocation misalignment.
//  * phases computed once per row per block (4 sincosf/block, smem bcast).

#define LQ      12
#define NROWS   4096
#define NBATCH  256
#define NELEMS  (NROWS * NBATCH)      // 1,048,576
#define ELEMS_PER_BLOCK 1024          // 256 threads x 4 elements = 4 rows
#define NBLOCKS (NELEMS / ELEMS_PER_BLOCK)  // 1024

__global__ void __launch_bounds__(256)
rz_kernel(const void* __restrict__ xraw, int x_elems,
          const void* __restrict__ araw,
          float* __restrict__ outf, int n_out_floats,
          int interleaved, int x_hint, int a_hint)
{
    __shared__ float2 s_phase[4];
    __shared__ int    s_xbf;

    const int t = threadIdx.x;

    // ---- dtype probe (block-uniform, reads 128 bytes of x) ----
    if (t == 0) {
        int xbf = x_hint;
        if (xbf < 0) {
            // Low 16 bits of each 32-bit word: bf16-pair data puts a bf16
            // normal sample there (exponent ~[117,132]); f32 data puts
            // random mantissa bits (~6% chance in-window).
            const unsigned short* h = (const unsigned short*)xraw;
            int match = 0;
            for (int i = 0; i < 32; ++i) {
                const int e = (h[2 * i] >> 7) & 0xFF;
                if (e >= 117 && e <= 132) ++match;
            }
            xbf = (match >= 24) ? 1 : 0;
        }
        s_xbf = xbf;
    }
    __syncthreads();
    const int xbf = s_xbf;

    // ---- per-row phase table: rows 4*b .. 4*b+3 ----
    if (t < 4) {
        const int abf = (a_hint >= 0) ? a_hint : xbf;
        const int row = 4 * blockIdx.x + t;
        float th = 0.0f;
#pragma unroll
        for (int i = 0; i < LQ; ++i) {
            float a;
            if (abf) a = __bfloat162float(((const __nv_bfloat16*)araw)[i]);
            else     a = ((const float*)araw)[i];
            const int bit = (row >> (LQ - 1 - i)) & 1;
            th = fmaf(a, bit ? -1.0f : 1.0f, th);
        }
        th *= -0.5f;
        float sn, cs;
        sincosf(th, &sn, &cs);
        s_phase[t] = make_float2(cs, sn);
    }
    __syncthreads();

    // ---- stream 4 consecutive elements per thread (same row) ----
    const int   e0 = blockIdx.x * ELEMS_PER_BLOCK + 4 * t;
    const float2 p = s_phase[t >> 6];   // (4*t)>>8 == t>>6

    float v[4];
#pragma unroll
    for (int j = 0; j < 4; ++j) {
        const int e = e0 + j;
        if (e < x_elems) {
            if (xbf) v[j] = __bfloat162float(((const __nv_bfloat16*)xraw)[e]);
            else     v[j] = ((const float*)xraw)[e];
        } else {
            v[j] = 0.0f;
        }
    }

    if (interleaved) {
#pragma unroll
        for (int j = 0; j < 4; ++j) {
            const int idx = 2 * (e0 + j);
            if (idx + 1 < n_out_floats) {
                outf[idx]     = p.x * v[j];
                outf[idx + 1] = p.y * v[j];
            }
        }
    } else {
#pragma unroll
        for (int j = 0; j < 4; ++j) {
            const int e = e0 + j;
            if (e < n_out_floats) outf[e] = p.x * v[j];
        }
    }
}

extern "C" void kernel_launch(void* const* d_in, const int* in_sizes, int n_in,
                              void* d_out, int out_size)
{
    // Identify: x = largest input; angle = input sized 12/24/48.
    int ix = -1, ia = -1;
    for (int i = 0; i < n_in; ++i) {
        const int sz = in_sizes[i];
        if (sz == 12 || sz == 24 || sz == 48) {
            ia = i;
        } else if (ix < 0 || sz > in_sizes[ix]) {
            ix = i;
        }
    }
    if (ix < 0) return;                 // nothing sensible to do
    if (ia < 0) ia = (n_in > 1) ? 1 : ix;

    const void* x = d_in[ix];
    const void* a = d_in[ia];

    // dtype hints from unambiguous byte-counted sizes.
    int x_hint = -1;
    if (in_sizes[ix] == 4 * NELEMS) x_hint = 0;   // f32 bytes
    int a_hint = -1;
    if (in_sizes[ia] == 48) a_hint = 0;           // f32 bytes
    else if (in_sizes[ia] == 24) a_hint = 1;      // bf16 bytes

    // Read bound in ELEMENTS of the detected dtype: min(size, NELEMS) is
    // safe under all (elements|bytes) x (f32|bf16) combinations.
    int x_elems = in_sizes[ix];
    if (x_elems > NELEMS) x_elems = NELEMS;

    // Output mode from out_size (elements of __output__ dtype):
    //   >= 2*NELEMS : complex64 viewed as float pairs -> interleaved, 8 MB
    //   == NELEMS   : float32 (numpy complex->float cast = REAL part), 4 MB
    //   else        : clamped real-only (diagnostic, cannot fault)
    int interleaved, n_out_floats;
    if (out_size >= 2 * NELEMS) {
        interleaved  = 1;
        n_out_floats = 2 * NELEMS;
    } else if (out_size >= NELEMS) {
        interleaved  = 0;
        n_out_floats = NELEMS;
    } else {
        interleaved  = 0;
        n_out_floats = out_size > 0 ? out_size : 0;
    }

    rz_kernel<<<NBLOCKS, 256>>>(x, x_elems, a,
                                (float*)d_out, n_out_floats,
                                interleaved, x_hint, a_hint);
}

// round 8
// speedup vs baseline: 1.0090x; 1.0090x over previous
#include <cuda_runtime.h>
#include <cuda_bf16.h>
#include <stdint.h>

// RZGate, L=12, D=2, J=1.  S = diag(1,-1) deterministically, so
// U = kron_i diag(e^{-i a_i/2}, e^{+i a_i/2}) is DIAGONAL:
//   theta(row) = -0.5 * sum_i a_i * (bit_i(row) ? -1 : +1)   (site 0 = MSB)
//   out[row,b] = (cos th + i sin th) * x[row,b]   (complex64 interleaved)
//
// GROUND TRUTH from round 6 (first pass): ABI is x f32[1M], out = 8 MB
// interleaved complex; the rounds 3-5 faults were MISALIGNED vector
// accesses (sub-allocated buffers lack 16B alignment), not OOB.
//
// This round: host-side alignment check chooses
//   * FAST path: float4 loads/stores, 8 elems/thread, warp == row,
//     one sincosf per row per block (smem broadcast).
//   * SAFE path: the proven all-scalar kernel from round 6 (no regression).

#define LQ      12
#define NROWS   4096
#define NBATCH  256
#define NELEMS  (NROWS * NBATCH)      // 1,048,576

// ---------------------------------------------------------------------------
// FAST kernel: f32, 16B-aligned x and out, full-size buffers.
// Block = 256 threads, 8 elements/thread -> 2048 elements = 8 rows per block.
// Warp w (t>>5) handles exactly row 8*blk + w -> phase is warp-uniform.
// ---------------------------------------------------------------------------
__global__ void __launch_bounds__(256)
rz_fast(const float4* __restrict__ x4,
        const float*  __restrict__ ang,
        float4*       __restrict__ out4)
{
    __shared__ float2 s_phase[8];

    const int t = threadIdx.x;

    if (t < 8) {
        const int row = 8 * blockIdx.x + t;
        float th = 0.0f;
#pragma unroll
        for (int i = 0; i < LQ; ++i) {
            const int bit = (row >> (LQ - 1 - i)) & 1;
            th = fmaf(ang[i], bit ? -1.0f : 1.0f, th);
        }
        th *= -0.5f;
        float sn, cs;
        sincosf(th, &sn, &cs);
        s_phase[t] = make_float2(cs, sn);
    }
    __syncthreads();

    const float2 p = s_phase[t >> 5];          // warp-uniform row phase

    const int xi = blockIdx.x * 512 + 2 * t;   // float4 index into x
    const float4 v0 = x4[xi];
    const float4 v1 = x4[xi + 1];

    const int oi = blockIdx.x * 1024 + 4 * t;  // float4 index into out
    out4[oi + 0] = make_float4(p.x * v0.x, p.y * v0.x, p.x * v0.y, p.y * v0.y);
    out4[oi + 1] = make_float4(p.x * v0.z, p.y * v0.z, p.x * v0.w, p.y * v0.w);
    out4[oi + 2] = make_float4(p.x * v1.x, p.y * v1.x, p.x * v1.y, p.y * v1.y);
    out4[oi + 3] = make_float4(p.x * v1.z, p.y * v1.z, p.x * v1.w, p.y * v1.w);
}

// ---------------------------------------------------------------------------
// SAFE kernel: all-scalar, dtype-probing, bounds-clamped (round-6 proven).
// ---------------------------------------------------------------------------
#define ELEMS_PER_BLOCK 1024
#define NBLOCKS_SAFE (NELEMS / ELEMS_PER_BLOCK)

__global__ void __launch_bounds__(256)
rz_safe(const void* __restrict__ xraw, int x_elems,
        const void* __restrict__ araw,
        float* __restrict__ outf, int n_out_floats,
        int interleaved, int x_hint, int a_hint)
{
    __shared__ float2 s_phase[4];
    __shared__ int    s_xbf;

    const int t = threadIdx.x;

    if (t == 0) {
        int xbf = x_hint;
        if (xbf < 0) {
            const unsigned short* h = (const unsigned short*)xraw;
            int match = 0;
            for (int i = 0; i < 32; ++i) {
                const int e = (h[2 * i] >> 7) & 0xFF;
                if (e >= 117 && e <= 132) ++match;
            }
            xbf = (match >= 24) ? 1 : 0;
        }
        s_xbf = xbf;
    }
    __syncthreads();
    const int xbf = s_xbf;

    if (t < 4) {
        const int abf = (a_hint >= 0) ? a_hint : xbf;
        const int row = 4 * blockIdx.x + t;
        float th = 0.0f;
#pragma unroll
        for (int i = 0; i < LQ; ++i) {
            float a;
            if (abf) a = __bfloat162float(((const __nv_bfloat16*)araw)[i]);
            else     a = ((const float*)araw)[i];
            const int bit = (row >> (LQ - 1 - i)) & 1;
            th = fmaf(a, bit ? -1.0f : 1.0f, th);
        }
        th *= -0.5f;
        float sn, cs;
        sincosf(th, &sn, &cs);
        s_phase[t] = make_float2(cs, sn);
    }
    __syncthreads();

    const int    e0 = blockIdx.x * ELEMS_PER_BLOCK + 4 * t;
    const float2 p  = s_phase[t >> 6];

    float v[4];
#pragma unroll
    for (int j = 0; j < 4; ++j) {
        const int e = e0 + j;
        if (e < x_elems) {
            if (xbf) v[j] = __bfloat162float(((const __nv_bfloat16*)xraw)[e]);
            else     v[j] = ((const float*)xraw)[e];
        } else {
            v[j] = 0.0f;
        }
    }

    if (interleaved) {
#pragma unroll
        for (int j = 0; j < 4; ++j) {
            const int idx = 2 * (e0 + j);
            if (idx + 1 < n_out_floats) {
                outf[idx]     = p.x * v[j];
                outf[idx + 1] = p.y * v[j];
            }
        }
    } else {
#pragma unroll
        for (int j = 0; j < 4; ++j) {
            const int e = e0 + j;
            if (e < n_out_floats) outf[e] = p.x * v[j];
        }
    }
}

extern "C" void kernel_launch(void* const* d_in, const int* in_sizes, int n_in,
                              void* d_out, int out_size)
{
    // Identify: x = largest input; angle = input sized 12/24/48.
    int ix = -1, ia = -1;
    for (int i = 0; i < n_in; ++i) {
        const int sz = in_sizes[i];
        if (sz == 12 || sz == 24 || sz == 48) {
            ia = i;
        } else if (ix < 0 || sz > in_sizes[ix]) {
            ix = i;
        }
    }
    if (ix < 0) return;
    if (ia < 0) ia = (n_in > 1) ? 1 : ix;

    const void* x = d_in[ix];
    const void* a = d_in[ia];

    int x_hint = -1;
    if (in_sizes[ix] == 4 * NELEMS) x_hint = 0;
    int a_hint = -1;
    if (in_sizes[ia] == 48) a_hint = 0;
    else if (in_sizes[ia] == 24) a_hint = 1;

    int x_elems = in_sizes[ix];
    if (x_elems > NELEMS) x_elems = NELEMS;

    int interleaved, n_out_floats;
    if (out_size >= 2 * NELEMS)      { interleaved = 1; n_out_floats = 2 * NELEMS; }
    else if (out_size >= NELEMS)     { interleaved = 0; n_out_floats = NELEMS; }
    else                             { interleaved = 0; n_out_floats = out_size > 0 ? out_size : 0; }

    // FAST path eligibility: interleaved complex output, full-size f32-like x
    // (in_sizes[ix] >= NELEMS elements, which round 6 validated as f32 data),
    // 16B-aligned x and out, 4B-aligned angle.
    const bool aligned16 =
        (((uintptr_t)x & 15u) == 0) && (((uintptr_t)d_out & 15u) == 0) &&
        (((uintptr_t)a & 3u)  == 0);
    const bool fast_ok = interleaved && aligned16 &&
                         x_elems == NELEMS && (a_hint != 1);

    if (fast_ok) {
        // 512 blocks x 256 threads, 8 elements/thread.
        rz_fast<<<NELEMS / 2048, 256>>>((const float4*)x, (const float*)a,
                                        (float4*)d_out);
    } else {
        rz_safe<<<NBLOCKS_SAFE, 256>>>(x, x_elems, a,
                                       (float*)d_out, n_out_floats,
                                       interleaved, x_hint, a_hint);
    }
}